// round 1
// baseline (speedup 1.0000x reference)
#include <cuda_runtime.h>

#define BATCH 256
#define SEQ   512
#define DIM   7
#define PADDIM 12            // floats per padded row (48B -> conflict-free LDS.128)
#define ROWS_PER_WARP 8
#define WARPS_PER_CTA 4
#define ROWS_PER_CTA (ROWS_PER_WARP * WARPS_PER_CTA)   // 32
#define NTILE (SEQ / ROWS_PER_CTA)                      // 16

// Scratch: projected (P) and biased (V), padded rows of 3 float4 each.
__device__ float4 g_P[BATCH * SEQ * 3];
__device__ float4 g_V[BATCH * SEQ * 3];

// ---------- packed f32x2 helpers (Blackwell-only, PTX required) ----------
__device__ __forceinline__ unsigned long long pk2(float a, float b) {
    unsigned long long r;
    asm("mov.b64 %0, {%1, %2};" : "=l"(r) : "f"(a), "f"(b));
    return r;
}
__device__ __forceinline__ void upk2(unsigned long long v, float& a, float& b) {
    asm("mov.b64 {%0, %1}, %2;" : "=f"(a), "=f"(b) : "l"(v));
}
__device__ __forceinline__ unsigned long long fma2_(unsigned long long a,
                                                    unsigned long long b,
                                                    unsigned long long c) {
    unsigned long long d;
    asm("fma.rn.f32x2 %0, %1, %2, %3;" : "=l"(d) : "l"(a), "l"(b), "l"(c));
    return d;
}
__device__ __forceinline__ unsigned long long mul2_(unsigned long long a,
                                                    unsigned long long b) {
    unsigned long long d;
    asm("mul.rn.f32x2 %0, %1, %2;" : "=l"(d) : "l"(a), "l"(b));
    return d;
}
__device__ __forceinline__ float ex2f(float x) {
    float y; asm("ex2.approx.f32 %0, %1;" : "=f"(y) : "f"(x)); return y;
}
__device__ __forceinline__ float rcpf(float x) {
    float y; asm("rcp.approx.f32 %0, %1;" : "=f"(y) : "f"(x)); return y;
}

// ---------- Kernel 1: biased = features + agent_bias; projected = biased @ W^T + b ----------
__global__ void prep_kernel(const float* __restrict__ feat,
                            const float* __restrict__ W,
                            const float* __restrict__ bia,
                            const float* __restrict__ abias) {
    int idx = blockIdx.x * blockDim.x + threadIdx.x;   // (b*SEQ + t)
    if (idx >= BATCH * SEQ) return;
    float f[7];
    const float* fp = feat + idx * 7;
#pragma unroll
    for (int d = 0; d < 7; d++) f[d] = fp[d] + __ldg(&abias[d]);
    float p[7];
#pragma unroll
    for (int e = 0; e < 7; e++) {
        float s = __ldg(&bia[e]);
#pragma unroll
        for (int d = 0; d < 7; d++) s = fmaf(f[d], __ldg(&W[e * 7 + d]), s);
        p[e] = s;
    }
    g_V[idx * 3 + 0] = make_float4(f[0], f[1], f[2], f[3]);
    g_V[idx * 3 + 1] = make_float4(f[4], f[5], f[6], 0.f);
    g_V[idx * 3 + 2] = make_float4(0.f, 0.f, 0.f, 0.f);
    g_P[idx * 3 + 0] = make_float4(p[0], p[1], p[2], p[3]);
    g_P[idx * 3 + 1] = make_float4(p[4], p[5], p[6], 0.f);
    g_P[idx * 3 + 2] = make_float4(0.f, 0.f, 0.f, 0.f);
}

// ---------- Kernel 2: scores -> softmax -> weights out + attended + LayerNorm ----------
// smem: sP [SEQ*PADDIM] + sV [SEQ*PADDIM] + score buffer [WARPS*8*SEQ]
#define SMEM_FLOATS (2 * SEQ * PADDIM + WARPS_PER_CTA * ROWS_PER_WARP * SEQ)
#define SMEM_BYTES  (SMEM_FLOATS * 4)

__global__ __launch_bounds__(128) void attn_kernel(
    float* __restrict__ outA, float* __restrict__ outW,
    const float* __restrict__ gamma, const float* __restrict__ beta) {
    extern __shared__ float sm[];
    float4* sP4 = reinterpret_cast<float4*>(sm);                  // SEQ*3 float4
    float4* sV4 = reinterpret_cast<float4*>(sm + SEQ * PADDIM);   // SEQ*3 float4
    float*  sB  = sm + 2 * SEQ * PADDIM;                          // warps*8*SEQ

    const int b    = blockIdx.y;
    const int tid  = threadIdx.x;
    const int lane = tid & 31;
    const int warp = tid >> 5;

    // Stage per-batch P/V tables into shared.
    const float4* gp = g_P + b * SEQ * 3;
    const float4* gv = g_V + b * SEQ * 3;
    for (int i = tid; i < SEQ * 3; i += 128) { sP4[i] = gp[i]; sV4[i] = gv[i]; }
    __syncthreads();

    const int row0 = blockIdx.x * ROWS_PER_CTA + warp * ROWS_PER_WARP;
    const float cfac = 1.4426950408889634f * rsqrtf(7.0f);  // log2(e)/sqrt(D)

    // q rows (scaled), packed as f32x2 pairs {q0,q1}{q2,q3}{q4,q5}{q6,0}
    unsigned long long q[ROWS_PER_WARP][4];
#pragma unroll
    for (int r = 0; r < ROWS_PER_WARP; r++) {
        const float* qp = sm + (row0 + r) * PADDIM;   // broadcast LDS
        q[r][0] = pk2(qp[0] * cfac, qp[1] * cfac);
        q[r][1] = pk2(qp[2] * cfac, qp[3] * cfac);
        q[r][2] = pk2(qp[4] * cfac, qp[5] * cfac);
        q[r][3] = pk2(qp[6] * cfac, 0.f);
    }

    unsigned long long acc[ROWS_PER_WARP][4];
    float sum[ROWS_PER_WARP];
#pragma unroll
    for (int r = 0; r < ROWS_PER_WARP; r++) {
        sum[r] = 0.f;
#pragma unroll
        for (int j = 0; j < 4; j++) acc[r][j] = 0ull;
    }

    float* myBuf = sB + warp * (ROWS_PER_WARP * SEQ);

#pragma unroll 1
    for (int tile = 0; tile < 8; tile++) {
        const int t0 = tile * 64 + lane;
        const int t1 = t0 + 32;
        float4 a0 = sP4[t0 * 3], a1 = sP4[t0 * 3 + 1];
        float4 b0 = sP4[t1 * 3], b1 = sP4[t1 * 3 + 1];
        float4 c0 = sV4[t0 * 3], c1 = sV4[t0 * 3 + 1];
        float4 d0 = sV4[t1 * 3], d1 = sV4[t1 * 3 + 1];
        unsigned long long pp0[4] = {pk2(a0.x,a0.y), pk2(a0.z,a0.w), pk2(a1.x,a1.y), pk2(a1.z,a1.w)};
        unsigned long long pp1[4] = {pk2(b0.x,b0.y), pk2(b0.z,b0.w), pk2(b1.x,b1.y), pk2(b1.z,b1.w)};
        unsigned long long vp0[4] = {pk2(c0.x,c0.y), pk2(c0.z,c0.w), pk2(c1.x,c1.y), pk2(c1.z,c1.w)};
        unsigned long long vp1[4] = {pk2(d0.x,d0.y), pk2(d0.z,d0.w), pk2(d1.x,d1.y), pk2(d1.z,d1.w)};
#pragma unroll
        for (int r = 0; r < ROWS_PER_WARP; r++) {
            unsigned long long z2 = mul2_(q[r][0], pp0[0]);
            z2 = fma2_(q[r][1], pp0[1], z2);
            z2 = fma2_(q[r][2], pp0[2], z2);
            z2 = fma2_(q[r][3], pp0[3], z2);
            float za, zb; upk2(z2, za, zb);
            float e0 = ex2f(za + zb);

            unsigned long long w2 = mul2_(q[r][0], pp1[0]);
            w2 = fma2_(q[r][1], pp1[1], w2);
            w2 = fma2_(q[r][2], pp1[2], w2);
            w2 = fma2_(q[r][3], pp1[3], w2);
            float wa, wb; upk2(w2, wa, wb);
            float e1 = ex2f(wa + wb);

            sum[r] += e0;
            sum[r] += e1;
            unsigned long long e0p = pk2(e0, e0);
            unsigned long long e1p = pk2(e1, e1);
#pragma unroll
            for (int j = 0; j < 4; j++) acc[r][j] = fma2_(e0p, vp0[j], acc[r][j]);
#pragma unroll
            for (int j = 0; j < 4; j++) acc[r][j] = fma2_(e1p, vp1[j], acc[r][j]);
            myBuf[r * SEQ + t0] = e0;
            myBuf[r * SEQ + t1] = e1;
        }
    }

    __syncwarp();

    // Row softmax denominators.
#pragma unroll
    for (int r = 0; r < ROWS_PER_WARP; r++) {
#pragma unroll
        for (int o = 16; o; o >>= 1) sum[r] += __shfl_xor_sync(0xffffffffu, sum[r], o);
    }

    // Normalize + write weights (coalesced STG.128, 512B per warp per op).
    if (outW) {
#pragma unroll 1
        for (int r = 0; r < ROWS_PER_WARP; r++) {
            float inv = rcpf(sum[r]);
            const float4* bw = reinterpret_cast<const float4*>(myBuf + r * SEQ);
            float4* gw = reinterpret_cast<float4*>(outW + (size_t)(b * SEQ + row0 + r) * SEQ);
#pragma unroll
            for (int c = 0; c < 4; c++) {
                float4 w = bw[c * 32 + lane];
                w.x *= inv; w.y *= inv; w.z *= inv; w.w *= inv;
                gw[c * 32 + lane] = w;
            }
        }
    }

    // Attended: cross-lane reduce, normalize by sum, LayerNorm, write.
    if (outA) {
        float gl = 0.f, bl = 0.f;
        if (lane < 7) { gl = __ldg(&gamma[lane]); bl = __ldg(&beta[lane]); }
#pragma unroll 1
        for (int r = 0; r < ROWS_PER_WARP; r++) {
            float a0,a1,a2,a3,a4,a5,a6,ax;
            upk2(acc[r][0], a0, a1);
            upk2(acc[r][1], a2, a3);
            upk2(acc[r][2], a4, a5);
            upk2(acc[r][3], a6, ax);
#pragma unroll
            for (int o = 16; o; o >>= 1) {
                a0 += __shfl_xor_sync(0xffffffffu, a0, o);
                a1 += __shfl_xor_sync(0xffffffffu, a1, o);
                a2 += __shfl_xor_sync(0xffffffffu, a2, o);
                a3 += __shfl_xor_sync(0xffffffffu, a3, o);
                a4 += __shfl_xor_sync(0xffffffffu, a4, o);
                a5 += __shfl_xor_sync(0xffffffffu, a5, o);
                a6 += __shfl_xor_sync(0xffffffffu, a6, o);
            }
            float inv = rcpf(sum[r]);
            a0 *= inv; a1 *= inv; a2 *= inv; a3 *= inv; a4 *= inv; a5 *= inv; a6 *= inv;
            float mu = (a0 + a1 + a2 + a3 + a4 + a5 + a6) * (1.0f / 7.0f);
            float e0 = a0 - mu, e1 = a1 - mu, e2 = a2 - mu, e3 = a3 - mu;
            float e4 = a4 - mu, e5 = a5 - mu, e6 = a6 - mu;
            float var = (e0*e0 + e1*e1 + e2*e2 + e3*e3 + e4*e4 + e5*e5 + e6*e6) * (1.0f / 7.0f);
            float rs = rsqrtf(var + 1e-5f);
            float sel = e0;
            if (lane == 1) sel = e1;
            if (lane == 2) sel = e2;
            if (lane == 3) sel = e3;
            if (lane == 4) sel = e4;
            if (lane == 5) sel = e5;
            if (lane == 6) sel = e6;
            if (lane < 7)
                outA[(size_t)(b * SEQ + row0 + r) * 7 + lane] = sel * rs * gl + bl;
        }
    }
}

extern "C" void kernel_launch(void* const* d_in, const int* in_sizes, int n_in,
                              void* d_out, int out_size) {
    const float* features = (const float*)d_in[0];
    const float* W        = (const float*)d_in[1];
    const float* bias     = (const float*)d_in[2];
    const float* abias    = (const float*)d_in[3];
    const float* gamma    = (const float*)d_in[4];
    const float* beta     = (const float*)d_in[5];

    float* out = (float*)d_out;
    const long long nA = (long long)BATCH * SEQ * DIM;       // 917504
    const long long nW = (long long)BATCH * SEQ * SEQ;       // 67108864
    float* outA = nullptr;
    float* outW = nullptr;
    long long total = (long long)out_size;
    if (total == nA + nW)      { outA = out; outW = out + nA; }
    else if (total == nW)      { outW = out; }
    else if (total == nA)      { outA = out; }
    else                       { outA = out; outW = out + nA; }  // best-effort default

    prep_kernel<<<(BATCH * SEQ + 255) / 256, 256>>>(features, W, bias, abias);

    cudaFuncSetAttribute(attn_kernel, cudaFuncAttributeMaxDynamicSharedMemorySize, SMEM_BYTES);
    attn_kernel<<<dim3(NTILE, BATCH), 128, SMEM_BYTES>>>(outA, outW, gamma, beta);
}

// round 2
// speedup vs baseline: 1.3427x; 1.3427x over previous
#include <cuda_runtime.h>

#define BATCH 256
#define SEQ   512
#define DIM   7
#define THREADS 256
#define WARPS   8
#define CHUNK   16

// Padded rows: 8 floats (2 float4) per row: [x0..x6, 0]
__device__ float4 g_P[BATCH * SEQ * 2];
__device__ float4 g_V[BATCH * SEQ * 2];

// ---------- packed f32x2 helpers (Blackwell-only, PTX required) ----------
__device__ __forceinline__ unsigned long long pk2(float a, float b) {
    unsigned long long r;
    asm("mov.b64 %0, {%1, %2};" : "=l"(r) : "f"(a), "f"(b));
    return r;
}
__device__ __forceinline__ void upk2(unsigned long long v, float& a, float& b) {
    asm("mov.b64 {%0, %1}, %2;" : "=f"(a), "=f"(b) : "l"(v));
}
__device__ __forceinline__ unsigned long long fma2_(unsigned long long a,
                                                    unsigned long long b,
                                                    unsigned long long c) {
    unsigned long long d;
    asm("fma.rn.f32x2 %0, %1, %2, %3;" : "=l"(d) : "l"(a), "l"(b), "l"(c));
    return d;
}
__device__ __forceinline__ unsigned long long mul2_(unsigned long long a,
                                                    unsigned long long b) {
    unsigned long long d;
    asm("mul.rn.f32x2 %0, %1, %2;" : "=l"(d) : "l"(a), "l"(b));
    return d;
}
__device__ __forceinline__ float ex2f(float x) {
    float y; asm("ex2.approx.f32 %0, %1;" : "=f"(y) : "f"(x)); return y;
}
__device__ __forceinline__ float rcpf(float x) {
    float y; asm("rcp.approx.f32 %0, %1;" : "=f"(y) : "f"(x)); return y;
}

// ---------- Kernel 1: biased + projected into padded global scratch ----------
__global__ void prep_kernel(const float* __restrict__ feat,
                            const float* __restrict__ W,
                            const float* __restrict__ bia,
                            const float* __restrict__ abias) {
    int idx = blockIdx.x * blockDim.x + threadIdx.x;   // (b*SEQ + t)
    if (idx >= BATCH * SEQ) return;
    float f[7];
    const float* fp = feat + idx * 7;
#pragma unroll
    for (int d = 0; d < 7; d++) f[d] = fp[d] + __ldg(&abias[d]);
    float p[7];
#pragma unroll
    for (int e = 0; e < 7; e++) {
        float s = __ldg(&bia[e]);
#pragma unroll
        for (int d = 0; d < 7; d++) s = fmaf(f[d], __ldg(&W[e * 7 + d]), s);
        p[e] = s;
    }
    g_V[idx * 2 + 0] = make_float4(f[0], f[1], f[2], f[3]);
    g_V[idx * 2 + 1] = make_float4(f[4], f[5], f[6], 0.f);
    g_P[idx * 2 + 0] = make_float4(p[0], p[1], p[2], p[3]);
    g_P[idx * 2 + 1] = make_float4(p[4], p[5], p[6], 0.f);
}

// ---------- Kernel 2: lane-owns-row attention ----------
// smem: sP 16KB + sV 16KB + eb 16KB = 48KB (static, 4 CTAs/SM)
__global__ __launch_bounds__(THREADS, 4) void attn_kernel(
    float* __restrict__ outA, float* __restrict__ outW,
    const float* __restrict__ gamma, const float* __restrict__ beta) {
    __shared__ float4 sP[SEQ * 2];
    __shared__ float4 sV[SEQ * 2];
    __shared__ float  eb[WARPS][CHUNK][32];

    const int b    = blockIdx.y;
    const int tid  = threadIdx.x;
    const int lane = tid & 31;
    const int warp = tid >> 5;

    // Stage this batch's padded P/V tables (32 KB).
    const float4* gp = g_P + b * SEQ * 2;
    const float4* gv = g_V + b * SEQ * 2;
#pragma unroll
    for (int i = 0; i < 4; i++) {
        sP[tid + i * THREADS] = gp[tid + i * THREADS];
        sV[tid + i * THREADS] = gv[tid + i * THREADS];
    }
    __syncthreads();

    const unsigned long long* sP64 = reinterpret_cast<const unsigned long long*>(sP);
    const unsigned long long* sV64 = reinterpret_cast<const unsigned long long*>(sV);

    // This thread's row (within batch) and its scaled query.
    const int rloc = blockIdx.x * THREADS + tid;       // 0..511
    const float cfac = 1.4426950408889634f * rsqrtf(7.0f);  // log2(e)/sqrt(D)
    const unsigned long long cf2 = pk2(cfac, cfac);

    unsigned long long q0 = mul2_(sP64[rloc * 4 + 0], cf2);
    unsigned long long q1 = mul2_(sP64[rloc * 4 + 1], cf2);
    unsigned long long q2 = mul2_(sP64[rloc * 4 + 2], cf2);
    unsigned long long q3 = mul2_(sP64[rloc * 4 + 3], cf2);
    // ensure pad slot of q is exactly 0 (pad*cfac = 0 anyway, but be safe)
    { float a, c; upk2(q3, a, c); q3 = pk2(a, 0.f); }

    // ---- Phase A: row sum + attended accumulator (no weight storage) ----
    unsigned long long acc0 = 0ull, acc1 = 0ull, acc2 = 0ull, acc3 = 0ull;
    float sum = 0.f;

#pragma unroll 4
    for (int t = 0; t < SEQ; t++) {
        unsigned long long p0 = sP64[t * 4 + 0];
        unsigned long long p1 = sP64[t * 4 + 1];
        unsigned long long p2 = sP64[t * 4 + 2];
        unsigned long long p3 = sP64[t * 4 + 3];
        unsigned long long z2 = mul2_(q0, p0);
        z2 = fma2_(q1, p1, z2);
        z2 = fma2_(q2, p2, z2);
        z2 = fma2_(q3, p3, z2);
        float za, zb; upk2(z2, za, zb);
        float e = ex2f(za + zb);
        sum += e;
        unsigned long long ee = pk2(e, e);
        acc0 = fma2_(ee, sV64[t * 4 + 0], acc0);
        acc1 = fma2_(ee, sV64[t * 4 + 1], acc1);
        acc2 = fma2_(ee, sV64[t * 4 + 2], acc2);
        acc3 = fma2_(ee, sV64[t * 4 + 3], acc3);
    }

    const float inv = rcpf(sum);

    // ---- Attended + LayerNorm (fully per-lane) ----
    if (outA) {
        float a0, a1, a2, a3, a4, a5, a6, ax;
        upk2(acc0, a0, a1);
        upk2(acc1, a2, a3);
        upk2(acc2, a4, a5);
        upk2(acc3, a6, ax);
        a0 *= inv; a1 *= inv; a2 *= inv; a3 *= inv; a4 *= inv; a5 *= inv; a6 *= inv;
        float mu = (a0 + a1 + a2 + a3 + a4 + a5 + a6) * (1.0f / 7.0f);
        float e0 = a0 - mu, e1 = a1 - mu, e2 = a2 - mu, e3 = a3 - mu;
        float e4 = a4 - mu, e5 = a5 - mu, e6 = a6 - mu;
        float var = (e0*e0 + e1*e1 + e2*e2 + e3*e3 + e4*e4 + e5*e5 + e6*e6) * (1.0f / 7.0f);
        float rs = rsqrtf(var + 1e-5f);
        float* oa = outA + (size_t)(b * SEQ + rloc) * 7;
        oa[0] = e0 * rs * __ldg(&gamma[0]) + __ldg(&beta[0]);
        oa[1] = e1 * rs * __ldg(&gamma[1]) + __ldg(&beta[1]);
        oa[2] = e2 * rs * __ldg(&gamma[2]) + __ldg(&beta[2]);
        oa[3] = e3 * rs * __ldg(&gamma[3]) + __ldg(&beta[3]);
        oa[4] = e4 * rs * __ldg(&gamma[4]) + __ldg(&beta[4]);
        oa[5] = e5 * rs * __ldg(&gamma[5]) + __ldg(&beta[5]);
        oa[6] = e6 * rs * __ldg(&gamma[6]) + __ldg(&beta[6]);
    }

    // ---- Phase B: recompute, normalize, transpose through smem, coalesced store ----
    if (outW) {
        const int wb = blockIdx.x * THREADS + warp * 32;   // warp's 32 rows (within batch)
        float (*ebw)[32] = eb[warp];
        const int tlo = lane & 15;
        const int half = lane >> 4;
        float* outBase = outW + (size_t)(b * SEQ + wb) * SEQ;

#pragma unroll 1
        for (int t0 = 0; t0 < SEQ; t0 += CHUNK) {
#pragma unroll
            for (int i = 0; i < CHUNK; i++) {
                const int t = t0 + i;
                unsigned long long z2 = mul2_(q0, sP64[t * 4 + 0]);
                z2 = fma2_(q1, sP64[t * 4 + 1], z2);
                z2 = fma2_(q2, sP64[t * 4 + 2], z2);
                z2 = fma2_(q3, sP64[t * 4 + 3], z2);
                float za, zb; upk2(z2, za, zb);
                // rotate slot by (lane + t) to kill bank conflicts on readback
                ebw[i][(lane + t) & 31] = ex2f(za + zb) * inv;
            }
            __syncwarp();
            const int tt = t0 + tlo;
#pragma unroll
            for (int rr = 0; rr < 32; rr += 2) {
                const int r = rr + half;
                float w = ebw[tlo][(r + tt) & 31];
                outBase[(size_t)r * SEQ + tt] = w;
            }
            __syncwarp();
        }
    }
}

extern "C" void kernel_launch(void* const* d_in, const int* in_sizes, int n_in,
                              void* d_out, int out_size) {
    const float* features = (const float*)d_in[0];
    const float* W        = (const float*)d_in[1];
    const float* bias     = (const float*)d_in[2];
    const float* abias    = (const float*)d_in[3];
    const float* gamma    = (const float*)d_in[4];
    const float* beta     = (const float*)d_in[5];

    float* out = (float*)d_out;
    const long long nA = (long long)BATCH * SEQ * DIM;       // 917504
    const long long nW = (long long)BATCH * SEQ * SEQ;       // 67108864
    float* outA = nullptr;
    float* outW = nullptr;
    long long total = (long long)out_size;
    if (total == nA + nW)      { outA = out; outW = out + nA; }
    else if (total == nW)      { outW = out; }
    else if (total == nA)      { outA = out; }
    else                       { outA = out; outW = out + nA; }

    prep_kernel<<<(BATCH * SEQ + 255) / 256, 256>>>(features, W, bias, abias);
    attn_kernel<<<dim3(SEQ / THREADS, BATCH), THREADS>>>(outA, outW, gamma, beta);
}

// round 3
// speedup vs baseline: 1.4152x; 1.0540x over previous
#include <cuda_runtime.h>

#define BATCH 256
#define SEQ   512
#define DIM   7
#define THREADS 64
#define NWARPS  2
#define RPT     4           // rows per thread
#define CHUNK   16          // t-chunk for phase B transpose buffer

// Padded rows: 8 floats (2 float4) per row: [x0..x6, 0]
__device__ float4 g_P[BATCH * SEQ * 2];
__device__ float4 g_V[BATCH * SEQ * 2];

// smem: sP (16KB) + sV (16KB) + eb (2 warps * 4 slots * 16 t * 33 floats)
#define EB_WARP_FLOATS (RPT * CHUNK * 33)
#define SMEM_FLOATS (2 * SEQ * 8 + NWARPS * EB_WARP_FLOATS)
#define SMEM_BYTES  (SMEM_FLOATS * 4)

// ---------- packed f32x2 helpers (Blackwell-only, PTX required) ----------
__device__ __forceinline__ unsigned long long pk2(float a, float b) {
    unsigned long long r;
    asm("mov.b64 %0, {%1, %2};" : "=l"(r) : "f"(a), "f"(b));
    return r;
}
__device__ __forceinline__ void upk2(unsigned long long v, float& a, float& b) {
    asm("mov.b64 {%0, %1}, %2;" : "=f"(a), "=f"(b) : "l"(v));
}
__device__ __forceinline__ unsigned long long fma2_(unsigned long long a,
                                                    unsigned long long b,
                                                    unsigned long long c) {
    unsigned long long d;
    asm("fma.rn.f32x2 %0, %1, %2, %3;" : "=l"(d) : "l"(a), "l"(b), "l"(c));
    return d;
}
__device__ __forceinline__ unsigned long long mul2_(unsigned long long a,
                                                    unsigned long long b) {
    unsigned long long d;
    asm("mul.rn.f32x2 %0, %1, %2;" : "=l"(d) : "l"(a), "l"(b));
    return d;
}
__device__ __forceinline__ float ex2f(float x) {
    float y; asm("ex2.approx.f32 %0, %1;" : "=f"(y) : "f"(x)); return y;
}
__device__ __forceinline__ float rcpf(float x) {
    float y; asm("rcp.approx.f32 %0, %1;" : "=f"(y) : "f"(x)); return y;
}

// ---------- Kernel 1: biased + projected into padded global scratch ----------
__global__ void prep_kernel(const float* __restrict__ feat,
                            const float* __restrict__ W,
                            const float* __restrict__ bia,
                            const float* __restrict__ abias) {
    int idx = blockIdx.x * blockDim.x + threadIdx.x;   // (b*SEQ + t)
    if (idx >= BATCH * SEQ) return;
    float f[7];
    const float* fp = feat + idx * 7;
#pragma unroll
    for (int d = 0; d < 7; d++) f[d] = fp[d] + __ldg(&abias[d]);
    float p[7];
#pragma unroll
    for (int e = 0; e < 7; e++) {
        float s = __ldg(&bia[e]);
#pragma unroll
        for (int d = 0; d < 7; d++) s = fmaf(f[d], __ldg(&W[e * 7 + d]), s);
        p[e] = s;
    }
    g_V[idx * 2 + 0] = make_float4(f[0], f[1], f[2], f[3]);
    g_V[idx * 2 + 1] = make_float4(f[4], f[5], f[6], 0.f);
    g_P[idx * 2 + 0] = make_float4(p[0], p[1], p[2], p[3]);
    g_P[idx * 2 + 1] = make_float4(p[4], p[5], p[6], 0.f);
}

// ---------- Kernel 2: 4-rows-per-thread attention ----------
__global__ __launch_bounds__(THREADS) void attn_kernel(
    float* __restrict__ outA, float* __restrict__ outW,
    const float* __restrict__ gamma, const float* __restrict__ beta) {
    extern __shared__ float sm[];
    float4* sP = reinterpret_cast<float4*>(sm);                // SEQ*2 float4
    float4* sV = reinterpret_cast<float4*>(sm + SEQ * 8);      // SEQ*2 float4
    float*  eb = sm + 2 * SEQ * 8;                             // per-warp buffers

    const int b    = blockIdx.y;
    const int tid  = threadIdx.x;
    const int lane = tid & 31;
    const int warp = tid >> 5;

    // Stage this batch's padded P/V tables (32 KB) with 64 threads.
    const float4* gp = g_P + b * SEQ * 2;
    const float4* gv = g_V + b * SEQ * 2;
#pragma unroll
    for (int i = 0; i < 16; i++) {
        sP[tid + i * THREADS] = gp[tid + i * THREADS];
        sV[tid + i * THREADS] = gv[tid + i * THREADS];
    }
    __syncthreads();

    const unsigned long long* sP64 = reinterpret_cast<const unsigned long long*>(sP);
    const unsigned long long* sV64 = reinterpret_cast<const unsigned long long*>(sV);

    // This thread's 4 rows (slot s -> row): base + s*32 + lane
    const int rowbase = blockIdx.x * 256 + warp * 128;   // within batch
    const float cfac = 1.4426950408889634f * rsqrtf(7.0f);  // log2(e)/sqrt(D)
    const unsigned long long cf2 = pk2(cfac, cfac);

    unsigned long long q[RPT][4];
#pragma unroll
    for (int s = 0; s < RPT; s++) {
        const int r = rowbase + s * 32 + lane;
        q[s][0] = mul2_(sP64[r * 4 + 0], cf2);
        q[s][1] = mul2_(sP64[r * 4 + 1], cf2);
        q[s][2] = mul2_(sP64[r * 4 + 2], cf2);
        q[s][3] = mul2_(sP64[r * 4 + 3], cf2);
        float a, c; upk2(q[s][3], a, c); q[s][3] = pk2(a, 0.f);
    }

    // ---- Phase A: row sums + attended accumulators ----
    unsigned long long acc[RPT][4];
    float sum[RPT];
#pragma unroll
    for (int s = 0; s < RPT; s++) {
        sum[s] = 0.f;
#pragma unroll
        for (int j = 0; j < 4; j++) acc[s][j] = 0ull;
    }

#pragma unroll 2
    for (int t = 0; t < SEQ; t++) {
        unsigned long long p0 = sP64[t * 4 + 0];
        unsigned long long p1 = sP64[t * 4 + 1];
        unsigned long long p2 = sP64[t * 4 + 2];
        unsigned long long p3 = sP64[t * 4 + 3];
        unsigned long long v0 = sV64[t * 4 + 0];
        unsigned long long v1 = sV64[t * 4 + 1];
        unsigned long long v2 = sV64[t * 4 + 2];
        unsigned long long v3 = sV64[t * 4 + 3];
#pragma unroll
        for (int s = 0; s < RPT; s++) {
            unsigned long long z2 = mul2_(q[s][0], p0);
            z2 = fma2_(q[s][1], p1, z2);
            z2 = fma2_(q[s][2], p2, z2);
            z2 = fma2_(q[s][3], p3, z2);
            float za, zb; upk2(z2, za, zb);
            float e = ex2f(za + zb);
            sum[s] += e;
            unsigned long long ee = pk2(e, e);
            acc[s][0] = fma2_(ee, v0, acc[s][0]);
            acc[s][1] = fma2_(ee, v1, acc[s][1]);
            acc[s][2] = fma2_(ee, v2, acc[s][2]);
            acc[s][3] = fma2_(ee, v3, acc[s][3]);
        }
    }

    float inv[RPT];
#pragma unroll
    for (int s = 0; s < RPT; s++) inv[s] = rcpf(sum[s]);

    // ---- Attended + LayerNorm (fully per-lane) ----
    if (outA) {
        float g0 = __ldg(&gamma[0]), g1 = __ldg(&gamma[1]), g2 = __ldg(&gamma[2]),
              g3 = __ldg(&gamma[3]), g4 = __ldg(&gamma[4]), g5 = __ldg(&gamma[5]),
              g6 = __ldg(&gamma[6]);
        float b0 = __ldg(&beta[0]), b1 = __ldg(&beta[1]), b2 = __ldg(&beta[2]),
              b3 = __ldg(&beta[3]), b4 = __ldg(&beta[4]), b5 = __ldg(&beta[5]),
              b6 = __ldg(&beta[6]);
#pragma unroll
        for (int s = 0; s < RPT; s++) {
            float a0, a1, a2, a3, a4, a5, a6, ax;
            upk2(acc[s][0], a0, a1);
            upk2(acc[s][1], a2, a3);
            upk2(acc[s][2], a4, a5);
            upk2(acc[s][3], a6, ax);
            float iv = inv[s];
            a0 *= iv; a1 *= iv; a2 *= iv; a3 *= iv; a4 *= iv; a5 *= iv; a6 *= iv;
            float mu = (a0 + a1 + a2 + a3 + a4 + a5 + a6) * (1.0f / 7.0f);
            float e0 = a0 - mu, e1 = a1 - mu, e2 = a2 - mu, e3 = a3 - mu;
            float e4 = a4 - mu, e5 = a5 - mu, e6 = a6 - mu;
            float var = (e0*e0 + e1*e1 + e2*e2 + e3*e3 + e4*e4 + e5*e5 + e6*e6) * (1.0f / 7.0f);
            float rs = rsqrtf(var + 1e-5f);
            float* oa = outA + (size_t)(b * SEQ + rowbase + s * 32 + lane) * 7;
            oa[0] = e0 * rs * g0 + b0;
            oa[1] = e1 * rs * g1 + b1;
            oa[2] = e2 * rs * g2 + b2;
            oa[3] = e3 * rs * g3 + b3;
            oa[4] = e4 * rs * g4 + b4;
            oa[5] = e5 * rs * g5 + b5;
            oa[6] = e6 * rs * g6 + b6;
        }
    }

    // ---- Phase B: recompute scores, normalize, transpose, STG.128 ----
    if (outW) {
        float* myeb = eb + warp * EB_WARP_FLOATS;   // [RPT][CHUNK][33]
        float* outBase = outW + (size_t)(b * SEQ + rowbase) * SEQ;
        const int r8 = lane >> 2;          // 0..7
        const int t4 = lane & 3;           // 0..3

#pragma unroll 1
        for (int t0 = 0; t0 < SEQ; t0 += CHUNK) {
#pragma unroll 2
            for (int i = 0; i < CHUNK; i++) {
                const int t = t0 + i;
                unsigned long long p0 = sP64[t * 4 + 0];
                unsigned long long p1 = sP64[t * 4 + 1];
                unsigned long long p2 = sP64[t * 4 + 2];
                unsigned long long p3 = sP64[t * 4 + 3];
#pragma unroll
                for (int s = 0; s < RPT; s++) {
                    unsigned long long z2 = mul2_(q[s][0], p0);
                    z2 = fma2_(q[s][1], p1, z2);
                    z2 = fma2_(q[s][2], p2, z2);
                    z2 = fma2_(q[s][3], p3, z2);
                    float za, zb; upk2(z2, za, zb);
                    myeb[(s * CHUNK + i) * 33 + lane] = ex2f(za + zb) * inv[s];
                }
            }
            __syncwarp();
#pragma unroll
            for (int s = 0; s < RPT; s++) {
#pragma unroll
                for (int g = 0; g < 4; g++) {
                    const int rr = g * 8 + r8;          // 0..31 row within slot
                    float4 w;
                    const float* src = myeb + s * (CHUNK * 33) + t4 * 4 * 33 + rr;
                    w.x = src[0 * 33];
                    w.y = src[1 * 33];
                    w.z = src[2 * 33];
                    w.w = src[3 * 33];
                    *reinterpret_cast<float4*>(
                        outBase + (size_t)(s * 32 + rr) * SEQ + t0 + t4 * 4) = w;
                }
            }
            __syncwarp();
        }
    }
}

extern "C" void kernel_launch(void* const* d_in, const int* in_sizes, int n_in,
                              void* d_out, int out_size) {
    const float* features = (const float*)d_in[0];
    const float* W        = (const float*)d_in[1];
    const float* bias     = (const float*)d_in[2];
    const float* abias    = (const float*)d_in[3];
    const float* gamma    = (const float*)d_in[4];
    const float* beta     = (const float*)d_in[5];

    float* out = (float*)d_out;
    const long long nA = (long long)BATCH * SEQ * DIM;       // 917504
    const long long nW = (long long)BATCH * SEQ * SEQ;       // 67108864
    float* outA = nullptr;
    float* outW = nullptr;
    long long total = (long long)out_size;
    if (total == nA + nW)      { outA = out; outW = out + nA; }
    else if (total == nW)      { outW = out; }
    else if (total == nA)      { outA = out; }
    else                       { outA = out; outW = out + nA; }

    prep_kernel<<<(BATCH * SEQ + 255) / 256, 256>>>(features, W, bias, abias);

    cudaFuncSetAttribute(attn_kernel, cudaFuncAttributeMaxDynamicSharedMemorySize, SMEM_BYTES);
    attn_kernel<<<dim3(2, BATCH), THREADS, SMEM_BYTES>>>(outA, outW, gamma, beta);
}

// round 5
// speedup vs baseline: 1.8907x; 1.3360x over previous
#include <cuda_runtime.h>

#define BATCH 256
#define SEQ   512
#define DIM   7
#define THREADS 128
#define RPT     2            // rows per thread (phase A)
#define ROWS_CTA 256         // rows covered per CTA (half batch)

// Padded rows: 8 floats (2 float4): [x0..x6, 0].  g_P is PRE-SCALED by sqrt(log2e/sqrt(7)).
__device__ float4 g_P[BATCH * SEQ * 2];
__device__ float4 g_V[BATCH * SEQ * 2];

// ---------- packed f32x2 helpers (Blackwell-only, PTX required) ----------
__device__ __forceinline__ unsigned long long pk2(float a, float b) {
    unsigned long long r;
    asm("mov.b64 %0, {%1, %2};" : "=l"(r) : "f"(a), "f"(b));
    return r;
}
__device__ __forceinline__ void upk2(unsigned long long v, float& a, float& b) {
    asm("mov.b64 {%0, %1}, %2;" : "=f"(a), "=f"(b) : "l"(v));
}
__device__ __forceinline__ unsigned long long fma2_(unsigned long long a,
                                                    unsigned long long b,
                                                    unsigned long long c) {
    unsigned long long d;
    asm("fma.rn.f32x2 %0, %1, %2, %3;" : "=l"(d) : "l"(a), "l"(b), "l"(c));
    return d;
}
__device__ __forceinline__ unsigned long long mul2_(unsigned long long a,
                                                    unsigned long long b) {
    unsigned long long d;
    asm("mul.rn.f32x2 %0, %1, %2;" : "=l"(d) : "l"(a), "l"(b));
    return d;
}
__device__ __forceinline__ unsigned long long add2_(unsigned long long a,
                                                    unsigned long long b) {
    unsigned long long d;
    asm("add.rn.f32x2 %0, %1, %2;" : "=l"(d) : "l"(a), "l"(b));
    return d;
}
__device__ __forceinline__ float ex2f(float x) {
    float y; asm("ex2.approx.f32 %0, %1;" : "=f"(y) : "f"(x)); return y;
}
__device__ __forceinline__ float lg2f(float x) {
    float y; asm("lg2.approx.f32 %0, %1;" : "=f"(y) : "f"(x)); return y;
}
__device__ __forceinline__ float rcpf(float x) {
    float y; asm("rcp.approx.f32 %0, %1;" : "=f"(y) : "f"(x)); return y;
}

// ---------- Kernel 1: biased + projected (pre-scaled) into padded scratch ----------
__global__ void prep_kernel(const float* __restrict__ feat,
                            const float* __restrict__ W,
                            const float* __restrict__ bia,
                            const float* __restrict__ abias) {
    int idx = blockIdx.x * blockDim.x + threadIdx.x;   // (b*SEQ + t)
    if (idx >= BATCH * SEQ) return;
    const float SC = 0.7384116545f;   // sqrt(log2(e)/sqrt(7))
    float f[7];
    const float* fp = feat + idx * 7;
#pragma unroll
    for (int d = 0; d < 7; d++) f[d] = fp[d] + __ldg(&abias[d]);
    float p[7];
#pragma unroll
    for (int e = 0; e < 7; e++) {
        float s = __ldg(&bia[e]);
#pragma unroll
        for (int d = 0; d < 7; d++) s = fmaf(f[d], __ldg(&W[e * 7 + d]), s);
        p[e] = s * SC;
    }
    g_V[idx * 2 + 0] = make_float4(f[0], f[1], f[2], f[3]);
    g_V[idx * 2 + 1] = make_float4(f[4], f[5], f[6], 0.f);
    g_P[idx * 2 + 0] = make_float4(p[0], p[1], p[2], p[3]);
    g_P[idx * 2 + 1] = make_float4(p[4], p[5], p[6], 0.f);
}

// ---------- Kernel 2 ----------
__global__ __launch_bounds__(THREADS) void attn_kernel(
    float* __restrict__ outA, float* __restrict__ outW,
    const float* __restrict__ gamma, const float* __restrict__ beta) {
    __shared__ float4 sP[SEQ * 2];        // 16 KB (pre-scaled projected)
    __shared__ float4 sV[SEQ * 2];        // 16 KB (biased values)
    __shared__ float  slinv[ROWS_CTA];    // -log2(rowsum)

    const int b    = blockIdx.y;
    const int half = blockIdx.x;          // 0/1 -> which 256 rows
    const int tid  = threadIdx.x;
    const int lane = tid & 31;
    const int warp = tid >> 5;

    // Stage this batch's padded P/V tables (32 KB).
    const float4* gp = g_P + b * SEQ * 2;
    const float4* gv = g_V + b * SEQ * 2;
#pragma unroll
    for (int i = 0; i < 8; i++) {
        sP[tid + i * THREADS] = gp[tid + i * THREADS];
        sV[tid + i * THREADS] = gv[tid + i * THREADS];
    }
    __syncthreads();

    const unsigned long long* sP64 = reinterpret_cast<const unsigned long long*>(sP);
    const unsigned long long* sV64 = reinterpret_cast<const unsigned long long*>(sV);

    const int rbase = half * ROWS_CTA;                  // CTA row offset in batch
    const int rloc0 = warp * (RPT * 32) + lane;         // local row of slot 0

    // q rows (already scaled): slot s -> local row rloc0 + s*32
    unsigned long long q[RPT][4];
#pragma unroll
    for (int s = 0; s < RPT; s++) {
        const int r = rbase + rloc0 + s * 32;
        q[s][0] = sP64[r * 4 + 0];
        q[s][1] = sP64[r * 4 + 1];
        q[s][2] = sP64[r * 4 + 2];
        q[s][3] = sP64[r * 4 + 3];
    }

    // ---- Phase A: row sums + attended accumulators ----
    unsigned long long acc[RPT][4];
    float sum[RPT];
#pragma unroll
    for (int s = 0; s < RPT; s++) {
        sum[s] = 0.f;
#pragma unroll
        for (int j = 0; j < 4; j++) acc[s][j] = 0ull;
    }

#pragma unroll 4
    for (int t = 0; t < SEQ; t++) {
        unsigned long long p0 = sP64[t * 4 + 0];
        unsigned long long p1 = sP64[t * 4 + 1];
        unsigned long long p2 = sP64[t * 4 + 2];
        unsigned long long p3 = sP64[t * 4 + 3];
        unsigned long long v0 = sV64[t * 4 + 0];
        unsigned long long v1 = sV64[t * 4 + 1];
        unsigned long long v2 = sV64[t * 4 + 2];
        unsigned long long v3 = sV64[t * 4 + 3];
#pragma unroll
        for (int s = 0; s < RPT; s++) {
            unsigned long long z2 = mul2_(q[s][0], p0);
            z2 = fma2_(q[s][1], p1, z2);
            z2 = fma2_(q[s][2], p2, z2);
            z2 = fma2_(q[s][3], p3, z2);
            float za, zb; upk2(z2, za, zb);
            float e = ex2f(za + zb);
            sum[s] += e;
            unsigned long long ee = pk2(e, e);
            acc[s][0] = fma2_(ee, v0, acc[s][0]);
            acc[s][1] = fma2_(ee, v1, acc[s][1]);
            acc[s][2] = fma2_(ee, v2, acc[s][2]);
            acc[s][3] = fma2_(ee, v3, acc[s][3]);
        }
    }

    // linv for phase B; inv for attended.
#pragma unroll
    for (int s = 0; s < RPT; s++) slinv[rloc0 + s * 32] = -lg2f(sum[s]);

    // ---- Attended + LayerNorm (fully per-lane) ----
    if (outA) {
        float g0 = __ldg(&gamma[0]), g1 = __ldg(&gamma[1]), g2 = __ldg(&gamma[2]),
              g3 = __ldg(&gamma[3]), g4 = __ldg(&gamma[4]), g5 = __ldg(&gamma[5]),
              g6 = __ldg(&gamma[6]);
        float b0 = __ldg(&beta[0]), b1 = __ldg(&beta[1]), b2 = __ldg(&beta[2]),
              b3 = __ldg(&beta[3]), b4 = __ldg(&beta[4]), b5 = __ldg(&beta[5]),
              b6 = __ldg(&beta[6]);
#pragma unroll
        for (int s = 0; s < RPT; s++) {
            float a0, a1, a2, a3, a4, a5, a6, ax;
            upk2(acc[s][0], a0, a1);
            upk2(acc[s][1], a2, a3);
            upk2(acc[s][2], a4, a5);
            upk2(acc[s][3], a6, ax);
            float iv = rcpf(sum[s]);
            a0 *= iv; a1 *= iv; a2 *= iv; a3 *= iv; a4 *= iv; a5 *= iv; a6 *= iv;
            float mu = (a0 + a1 + a2 + a3 + a4 + a5 + a6) * (1.0f / 7.0f);
            float e0 = a0 - mu, e1 = a1 - mu, e2 = a2 - mu, e3 = a3 - mu;
            float e4 = a4 - mu, e5 = a5 - mu, e6 = a6 - mu;
            float var = (e0*e0 + e1*e1 + e2*e2 + e3*e3 + e4*e4 + e5*e5 + e6*e6) * (1.0f / 7.0f);
            float rs = rsqrtf(var + 1e-5f);
            float* oa = outA + (size_t)(b * SEQ + rbase + rloc0 + s * 32) * 7;
            oa[0] = e0 * rs * g0 + b0;
            oa[1] = e1 * rs * g1 + b1;
            oa[2] = e2 * rs * g2 + b2;
            oa[3] = e3 * rs * g3 + b3;
            oa[4] = e4 * rs * g4 + b4;
            oa[5] = e5 * rs * g5 + b5;
            oa[6] = e6 * rs * g6 + b6;
        }
    }
    __syncthreads();

    // ---- Phase B: lane-owns-t, direct coalesced weight stores ----
    if (outW) {
        // Warp owns t in [warp*128, warp*128+128), 4 subtiles of 32 (t = base + sub*32 + lane).
        const int tb = warp * 128;
        unsigned long long pt[4][4];
#pragma unroll
        for (int sub = 0; sub < 4; sub++) {
            const int t = tb + sub * 32 + lane;
#pragma unroll
            for (int j = 0; j < 4; j++) pt[sub][j] = sP64[t * 4 + j];
        }
        float* outBase = outW + ((size_t)(b * SEQ + rbase)) * SEQ + tb;

#pragma unroll 2
        for (int r = 0; r < ROWS_CTA; r++) {
            const float4 lo = sP[(rbase + r) * 2 + 0];   // uniform loads
            const float4 hi = sP[(rbase + r) * 2 + 1];
            const float  lv = slinv[r];
            const unsigned long long r0 = pk2(lo.x, lo.y);
            const unsigned long long r1 = pk2(lo.z, lo.w);
            const unsigned long long r2 = pk2(hi.x, hi.y);
            const unsigned long long r3 = pk2(hi.z, hi.w);   // pad slot is 0
            float* orow = outBase + (size_t)r * SEQ;
#pragma unroll
            for (int sub = 0; sub < 4; sub++) {
                unsigned long long z2 = mul2_(r0, pt[sub][0]);
                z2 = fma2_(r1, pt[sub][1], z2);
                z2 = fma2_(r2, pt[sub][2], z2);
                z2 = fma2_(r3, pt[sub][3], z2);
                float za, zb; upk2(z2, za, zb);
                orow[sub * 32 + lane] = ex2f(za + zb + lv);
            }
        }
    }
}

extern "C" void kernel_launch(void* const* d_in, const int* in_sizes, int n_in,
                              void* d_out, int out_size) {
    const float* features = (const float*)d_in[0];
    const float* W        = (const float*)d_in[1];
    const float* bias     = (const float*)d_in[2];
    const float* abias    = (const float*)d_in[3];
    const float* gamma    = (const float*)d_in[4];
    const float* beta     = (const float*)d_in[5];

    float* out = (float*)d_out;
    const long long nA = (long long)BATCH * SEQ * DIM;       // 917504
    const long long nW = (long long)BATCH * SEQ * SEQ;       // 67108864
    float* outA = nullptr;
    float* outW = nullptr;
    long long total = (long long)out_size;
    if (total == nA + nW)      { outA = out; outW = out + nA; }
    else if (total == nW)      { outW = out; }
    else if (total == nA)      { outA = out; }
    else                       { outA = out; outW = out + nA; }

    prep_kernel<<<(BATCH * SEQ + 255) / 256, 256>>>(features, W, bias, abias);
    attn_kernel<<<dim3(2, BATCH), THREADS>>>(outA, outW, gamma, beta);
}

// round 8
// speedup vs baseline: 1.9749x; 1.0445x over previous
#include <cuda_runtime.h>

#define BATCH 256
#define SEQ   512
#define DIM   7
#define THREADS 128
#define RPT     2            // rows per thread (phase A)
#define ROWS_CTA 256         // rows covered per CTA (half batch)

// ---------- packed f32x2 helpers (Blackwell-only, PTX required) ----------
__device__ __forceinline__ unsigned long long pk2(float a, float b) {
    unsigned long long r;
    asm("mov.b64 %0, {%1, %2};" : "=l"(r) : "f"(a), "f"(b));
    return r;
}
__device__ __forceinline__ void upk2(unsigned long long v, float& a, float& b) {
    asm("mov.b64 {%0, %1}, %2;" : "=f"(a), "=f"(b) : "l"(v));
}
__device__ __forceinline__ unsigned long long fma2_(unsigned long long a,
                                                    unsigned long long b,
                                                    unsigned long long c) {
    unsigned long long d;
    asm("fma.rn.f32x2 %0, %1, %2, %3;" : "=l"(d) : "l"(a), "l"(b), "l"(c));
    return d;
}
__device__ __forceinline__ unsigned long long mul2_(unsigned long long a,
                                                    unsigned long long b) {
    unsigned long long d;
    asm("mul.rn.f32x2 %0, %1, %2;" : "=l"(d) : "l"(a), "l"(b));
    return d;
}
__device__ __forceinline__ float ex2f(float x) {
    float y; asm("ex2.approx.f32 %0, %1;" : "=f"(y) : "f"(x)); return y;
}
__device__ __forceinline__ float lg2f(float x) {
    float y; asm("lg2.approx.f32 %0, %1;" : "=f"(y) : "f"(x)); return y;
}
__device__ __forceinline__ float rcpf(float x) {
    float y; asm("rcp.approx.f32 %0, %1;" : "=f"(y) : "f"(x)); return y;
}

// ---------- Single fused kernel ----------
__global__ __launch_bounds__(THREADS) void attn_kernel(
    const float* __restrict__ feat,
    const float* __restrict__ Wm,
    const float* __restrict__ bia,
    const float* __restrict__ abias,
    const float* __restrict__ gamma,
    const float* __restrict__ beta,
    float* __restrict__ outA, float* __restrict__ outW) {
    __shared__ float4 sP[SEQ * 2];        // 16 KB (pre-scaled projected, pad 0)
    __shared__ float4 sV[SEQ * 2];        // 16 KB (biased values, pad 0)
    __shared__ float  slinv[ROWS_CTA];    // -log2(rowsum)

    const int b    = blockIdx.y;
    const int half = blockIdx.x;          // 0/1 -> which 256 rows
    const int tid  = threadIdx.x;
    const int lane = tid & 31;
    const int warp = tid >> 5;

    // ---- Fused prep/staging: read features, project, scale, fill smem ----
    {
        const float SC = 0.7384116545f;   // sqrt(log2(e)/sqrt(7))
        float wr[7][7], br[7], ar[7];
#pragma unroll
        for (int e = 0; e < 7; e++) {
            br[e] = __ldg(&bia[e]);
            ar[e] = __ldg(&abias[e]);
#pragma unroll
            for (int d = 0; d < 7; d++) wr[e][d] = __ldg(&Wm[e * 7 + d]);
        }
#pragma unroll
        for (int i = 0; i < 4; i++) {
            const int r = tid + i * THREADS;          // 0..511
            const float* fp = feat + ((size_t)b * SEQ + r) * 7;
            float f[7];
#pragma unroll
            for (int d = 0; d < 7; d++) f[d] = fp[d] + ar[d];
            float p[7];
#pragma unroll
            for (int e = 0; e < 7; e++) {
                float s = br[e];
#pragma unroll
                for (int d = 0; d < 7; d++) s = fmaf(f[d], wr[e][d], s);
                p[e] = s * SC;
            }
            sV[r * 2 + 0] = make_float4(f[0], f[1], f[2], f[3]);
            sV[r * 2 + 1] = make_float4(f[4], f[5], f[6], 0.f);
            sP[r * 2 + 0] = make_float4(p[0], p[1], p[2], p[3]);
            sP[r * 2 + 1] = make_float4(p[4], p[5], p[6], 0.f);
        }
    }
    __syncthreads();

    const unsigned long long* sP64 = reinterpret_cast<const unsigned long long*>(sP);
    const unsigned long long* sV64 = reinterpret_cast<const unsigned long long*>(sV);

    const int rbase = half * ROWS_CTA;                  // CTA row offset in batch
    const int rloc0 = warp * (RPT * 32) + lane;         // local row of slot 0

    unsigned long long q[RPT][4];
#pragma unroll
    for (int s = 0; s < RPT; s++) {
        const int r = rbase + rloc0 + s * 32;
        q[s][0] = sP64[r * 4 + 0];
        q[s][1] = sP64[r * 4 + 1];
        q[s][2] = sP64[r * 4 + 2];
        q[s][3] = sP64[r * 4 + 3];
    }

    // ---- Phase A: row sums + attended accumulators ----
    unsigned long long acc[RPT][4];
    float sum[RPT];
#pragma unroll
    for (int s = 0; s < RPT; s++) {
        sum[s] = 0.f;
#pragma unroll
        for (int j = 0; j < 4; j++) acc[s][j] = 0ull;
    }

#pragma unroll 4
    for (int t = 0; t < SEQ; t++) {
        unsigned long long p0 = sP64[t * 4 + 0];
        unsigned long long p1 = sP64[t * 4 + 1];
        unsigned long long p2 = sP64[t * 4 + 2];
        unsigned long long p3 = sP64[t * 4 + 3];
        unsigned long long v0 = sV64[t * 4 + 0];
        unsigned long long v1 = sV64[t * 4 + 1];
        unsigned long long v2 = sV64[t * 4 + 2];
        unsigned long long v3 = sV64[t * 4 + 3];
#pragma unroll
        for (int s = 0; s < RPT; s++) {
            unsigned long long z2 = mul2_(q[s][0], p0);
            z2 = fma2_(q[s][1], p1, z2);
            z2 = fma2_(q[s][2], p2, z2);
            z2 = fma2_(q[s][3], p3, z2);
            float za, zb; upk2(z2, za, zb);
            float e = ex2f(za + zb);
            sum[s] += e;
            unsigned long long ee = pk2(e, e);
            acc[s][0] = fma2_(ee, v0, acc[s][0]);
            acc[s][1] = fma2_(ee, v1, acc[s][1]);
            acc[s][2] = fma2_(ee, v2, acc[s][2]);
            acc[s][3] = fma2_(ee, v3, acc[s][3]);
        }
    }

#pragma unroll
    for (int s = 0; s < RPT; s++) slinv[rloc0 + s * 32] = -lg2f(sum[s]);
    __syncthreads();

    // ---- Attended + LayerNorm (fully per-lane; overlaps other warps' phase B) ----
    if (outA) {
        float g0 = __ldg(&gamma[0]), g1 = __ldg(&gamma[1]), g2 = __ldg(&gamma[2]),
              g3 = __ldg(&gamma[3]), g4 = __ldg(&gamma[4]), g5 = __ldg(&gamma[5]),
              g6 = __ldg(&gamma[6]);
        float b0 = __ldg(&beta[0]), b1 = __ldg(&beta[1]), b2 = __ldg(&beta[2]),
              b3 = __ldg(&beta[3]), b4 = __ldg(&beta[4]), b5 = __ldg(&beta[5]),
              b6 = __ldg(&beta[6]);
#pragma unroll
        for (int s = 0; s < RPT; s++) {
            float a0, a1, a2, a3, a4, a5, a6, ax;
            upk2(acc[s][0], a0, a1);
            upk2(acc[s][1], a2, a3);
            upk2(acc[s][2], a4, a5);
            upk2(acc[s][3], a6, ax);
            float iv = rcpf(sum[s]);
            a0 *= iv; a1 *= iv; a2 *= iv; a3 *= iv; a4 *= iv; a5 *= iv; a6 *= iv;
            float mu = (a0 + a1 + a2 + a3 + a4 + a5 + a6) * (1.0f / 7.0f);
            float e0 = a0 - mu, e1 = a1 - mu, e2 = a2 - mu, e3 = a3 - mu;
            float e4 = a4 - mu, e5 = a5 - mu, e6 = a6 - mu;
            float var = (e0*e0 + e1*e1 + e2*e2 + e3*e3 + e4*e4 + e5*e5 + e6*e6) * (1.0f / 7.0f);
            float rs = rsqrtf(var + 1e-5f);
            float* oa = outA + (size_t)(b * SEQ + rbase + rloc0 + s * 32) * 7;
            oa[0] = e0 * rs * g0 + b0;
            oa[1] = e1 * rs * g1 + b1;
            oa[2] = e2 * rs * g2 + b2;
            oa[3] = e3 * rs * g3 + b3;
            oa[4] = e4 * rs * g4 + b4;
            oa[5] = e5 * rs * g5 + b5;
            oa[6] = e6 * rs * g6 + b6;
        }
    }

    // ---- Phase B: lane owns t-quad, STG.128 coalesced weight stores ----
    if (outW) {
        const int tb = warp * 128;        // warp's 128 t-columns
        // lane owns t = tb + lane*4 + j (one-time bank-conflicted load, amortized)
        unsigned long long pt[4][4];
#pragma unroll
        for (int j = 0; j < 4; j++) {
            const int t = tb + lane * 4 + j;
#pragma unroll
            for (int k = 0; k < 4; k++) pt[j][k] = sP64[t * 4 + k];
        }
        float* outBase = outW + ((size_t)(b * SEQ + rbase)) * SEQ + tb;

#pragma unroll 2
        for (int r = 0; r < ROWS_CTA; r++) {
            const float4 lo = sP[(rbase + r) * 2 + 0];   // uniform loads
            const float4 hi = sP[(rbase + r) * 2 + 1];
            const unsigned long long lv2 = pk2(slinv[r], 0.f);
            const unsigned long long r0 = pk2(lo.x, lo.y);
            const unsigned long long r1 = pk2(lo.z, lo.w);
            const unsigned long long r2 = pk2(hi.x, hi.y);
            const unsigned long long r3 = pk2(hi.z, hi.w);   // pad slot is 0
            float4 wv;
            {
                unsigned long long z2 = fma2_(r0, pt[0][0], lv2);
                z2 = fma2_(r1, pt[0][1], z2);
                z2 = fma2_(r2, pt[0][2], z2);
                z2 = fma2_(r3, pt[0][3], z2);
                float za, zb; upk2(z2, za, zb);
                wv.x = ex2f(za + zb);
            }
            {
                unsigned long long z2 = fma2_(r0, pt[1][0], lv2);
                z2 = fma2_(r1, pt[1][1], z2);
                z2 = fma2_(r2, pt[1][2], z2);
                z2 = fma2_(r3, pt[1][3], z2);
                float za, zb; upk2(z2, za, zb);
                wv.y = ex2f(za + zb);
            }
            {
                unsigned long long z2 = fma2_(r0, pt[2][0], lv2);
                z2 = fma2_(r1, pt[2][1], z2);
                z2 = fma2_(r2, pt[2][2], z2);
                z2 = fma2_(r3, pt[2][3], z2);
                float za, zb; upk2(z2, za, zb);
                wv.z = ex2f(za + zb);
            }
            {
                unsigned long long z2 = fma2_(r0, pt[3][0], lv2);
                z2 = fma2_(r1, pt[3][1], z2);
                z2 = fma2_(r2, pt[3][2], z2);
                z2 = fma2_(r3, pt[3][3], z2);
                float za, zb; upk2(z2, za, zb);
                wv.w = ex2f(za + zb);
            }
            *reinterpret_cast<float4*>(outBase + (size_t)r * SEQ + lane * 4) = wv;
        }
    }
}

extern "C" void kernel_launch(void* const* d_in, const int* in_sizes, int n_in,
                              void* d_out, int out_size) {
    const float* features = (const float*)d_in[0];
    const float* W        = (const float*)d_in[1];
    const float* bias     = (const float*)d_in[2];
    const float* abias    = (const float*)d_in[3];
    const float* gamma    = (const float*)d_in[4];
    const float* beta     = (const float*)d_in[5];

    float* out = (float*)d_out;
    const long long nA = (long long)BATCH * SEQ * DIM;       // 917504
    const long long nW = (long long)BATCH * SEQ * SEQ;       // 67108864
    float* outA = nullptr;
    float* outW = nullptr;
    long long total = (long long)out_size;
    if (total == nA + nW)      { outA = out; outW = out + nA; }
    else if (total == nW)      { outW = out; }
    else if (total == nA)      { outA = out; }
    else                       { outA = out; outW = out + nA; }

    attn_kernel<<<dim3(2, BATCH), THREADS>>>(features, W, bias, abias,
                                             gamma, beta, outA, outW);
}

// round 9
// speedup vs baseline: 2.0210x; 1.0234x over previous
#include <cuda_runtime.h>

#define BATCH 256
#define SEQ   512
#define DIM   7
#define THREADS 128
#define RPT     2            // rows per thread (phase A)
#define ROWS_CTA 256         // rows covered per CTA (half batch)

// ---------- packed f32x2 helpers (Blackwell-only, PTX required) ----------
__device__ __forceinline__ unsigned long long pk2(float a, float b) {
    unsigned long long r;
    asm("mov.b64 %0, {%1, %2};" : "=l"(r) : "f"(a), "f"(b));
    return r;
}
__device__ __forceinline__ void upk2(unsigned long long v, float& a, float& b) {
    asm("mov.b64 {%0, %1}, %2;" : "=f"(a), "=f"(b) : "l"(v));
}
__device__ __forceinline__ unsigned long long fma2_(unsigned long long a,
                                                    unsigned long long b,
                                                    unsigned long long c) {
    unsigned long long d;
    asm("fma.rn.f32x2 %0, %1, %2, %3;" : "=l"(d) : "l"(a), "l"(b), "l"(c));
    return d;
}
__device__ __forceinline__ unsigned long long mul2_(unsigned long long a,
                                                    unsigned long long b) {
    unsigned long long d;
    asm("mul.rn.f32x2 %0, %1, %2;" : "=l"(d) : "l"(a), "l"(b));
    return d;
}
__device__ __forceinline__ float ex2f(float x) {
    float y; asm("ex2.approx.f32 %0, %1;" : "=f"(y) : "f"(x)); return y;
}
__device__ __forceinline__ float lg2f(float x) {
    float y; asm("lg2.approx.f32 %0, %1;" : "=f"(y) : "f"(x)); return y;
}
__device__ __forceinline__ float rcpf(float x) {
    float y; asm("rcp.approx.f32 %0, %1;" : "=f"(y) : "f"(x)); return y;
}

// ---------- Single fused kernel ----------
__global__ __launch_bounds__(THREADS) void attn_kernel(
    const float* __restrict__ feat,
    const float* __restrict__ Wm,
    const float* __restrict__ bia,
    const float* __restrict__ abias,
    const float* __restrict__ gamma,
    const float* __restrict__ beta,
    float* __restrict__ outA, float* __restrict__ outW) {
    __shared__ float4 sP[SEQ * 2];        // 16 KB (pre-scaled projected, pad 0)
    __shared__ float4 sV[SEQ * 2];        // 16 KB (biased values, pad 1.0 -> row sums)
    __shared__ float  slinv[ROWS_CTA];    // -log2(rowsum)

    const int b    = blockIdx.y;
    const int half = blockIdx.x;          // 0/1 -> which 256 rows
    const int tid  = threadIdx.x;
    const int lane = tid & 31;
    const int warp = tid >> 5;

    // ---- Fused prep/staging: read features, project, scale, fill smem ----
    {
        const float SC = 0.7384116545f;   // sqrt(log2(e)/sqrt(7))
        float wr[7][7], br[7], ar[7];
#pragma unroll
        for (int e = 0; e < 7; e++) {
            br[e] = __ldg(&bia[e]);
            ar[e] = __ldg(&abias[e]);
#pragma unroll
            for (int d = 0; d < 7; d++) wr[e][d] = __ldg(&Wm[e * 7 + d]);
        }
#pragma unroll
        for (int i = 0; i < 4; i++) {
            const int r = tid + i * THREADS;          // 0..511
            const float* fp = feat + ((size_t)b * SEQ + r) * 7;
            float f[7];
#pragma unroll
            for (int d = 0; d < 7; d++) f[d] = fp[d] + ar[d];
            float p[7];
#pragma unroll
            for (int e = 0; e < 7; e++) {
                float s = br[e];
#pragma unroll
                for (int d = 0; d < 7; d++) s = fmaf(f[d], wr[e][d], s);
                p[e] = s * SC;
            }
            sV[r * 2 + 0] = make_float4(f[0], f[1], f[2], f[3]);
            sV[r * 2 + 1] = make_float4(f[4], f[5], f[6], 1.0f);  // pad=1 -> sum slot
            sP[r * 2 + 0] = make_float4(p[0], p[1], p[2], p[3]);
            sP[r * 2 + 1] = make_float4(p[4], p[5], p[6], 0.f);
        }
    }
    __syncthreads();

    const int rbase = half * ROWS_CTA;                  // CTA row offset in batch
    const int rloc0 = warp * (RPT * 32) + lane;         // local row of slot 0

    unsigned long long q[RPT][4];
#pragma unroll
    for (int s = 0; s < RPT; s++) {
        const int r = rbase + rloc0 + s * 32;
        float4 qa = sP[r * 2 + 0];
        float4 qb = sP[r * 2 + 1];
        q[s][0] = pk2(qa.x, qa.y);
        q[s][1] = pk2(qa.z, qa.w);
        q[s][2] = pk2(qb.x, qb.y);
        q[s][3] = pk2(qb.z, qb.w);   // pad 0
    }

    // ---- Phase A: attended accumulators; row sum rides in acc[s][3].hi ----
    unsigned long long acc[RPT][4];
#pragma unroll
    for (int s = 0; s < RPT; s++) {
#pragma unroll
        for (int j = 0; j < 4; j++) acc[s][j] = 0ull;
    }

#pragma unroll 4
    for (int t = 0; t < SEQ; t++) {
        const float4 pa = sP[t * 2 + 0];
        const float4 pb = sP[t * 2 + 1];
        const float4 va = sV[t * 2 + 0];
        const float4 vb = sV[t * 2 + 1];
        const unsigned long long p0 = pk2(pa.x, pa.y);
        const unsigned long long p1 = pk2(pa.z, pa.w);
        const unsigned long long p2 = pk2(pb.x, pb.y);
        const unsigned long long p3 = pk2(pb.z, pb.w);
        const unsigned long long v0 = pk2(va.x, va.y);
        const unsigned long long v1 = pk2(va.z, va.w);
        const unsigned long long v2 = pk2(vb.x, vb.y);
        const unsigned long long v3 = pk2(vb.z, vb.w);   // hi = 1.0 (sum slot)
#pragma unroll
        for (int s = 0; s < RPT; s++) {
            unsigned long long z2 = mul2_(q[s][0], p0);
            z2 = fma2_(q[s][1], p1, z2);
            z2 = fma2_(q[s][2], p2, z2);
            z2 = fma2_(q[s][3], p3, z2);
            float za, zb; upk2(z2, za, zb);
            const float e = ex2f(za + zb);
            const unsigned long long ee = pk2(e, e);
            acc[s][0] = fma2_(ee, v0, acc[s][0]);
            acc[s][1] = fma2_(ee, v1, acc[s][1]);
            acc[s][2] = fma2_(ee, v2, acc[s][2]);
            acc[s][3] = fma2_(ee, v3, acc[s][3]);
        }
    }

    float sum[RPT];
#pragma unroll
    for (int s = 0; s < RPT; s++) {
        float a6, sm; upk2(acc[s][3], a6, sm);
        sum[s] = sm;
        slinv[rloc0 + s * 32] = -lg2f(sm);
    }
    __syncthreads();

    // ---- Attended + LayerNorm (fully per-lane) ----
    if (outA) {
        float g0 = __ldg(&gamma[0]), g1 = __ldg(&gamma[1]), g2 = __ldg(&gamma[2]),
              g3 = __ldg(&gamma[3]), g4 = __ldg(&gamma[4]), g5 = __ldg(&gamma[5]),
              g6 = __ldg(&gamma[6]);
        float b0 = __ldg(&beta[0]), b1 = __ldg(&beta[1]), b2 = __ldg(&beta[2]),
              b3 = __ldg(&beta[3]), b4 = __ldg(&beta[4]), b5 = __ldg(&beta[5]),
              b6 = __ldg(&beta[6]);
#pragma unroll
        for (int s = 0; s < RPT; s++) {
            float a0, a1, a2, a3, a4, a5, a6, ax;
            upk2(acc[s][0], a0, a1);
            upk2(acc[s][1], a2, a3);
            upk2(acc[s][2], a4, a5);
            upk2(acc[s][3], a6, ax);
            float iv = rcpf(sum[s]);
            a0 *= iv; a1 *= iv; a2 *= iv; a3 *= iv; a4 *= iv; a5 *= iv; a6 *= iv;
            float mu = (a0 + a1 + a2 + a3 + a4 + a5 + a6) * (1.0f / 7.0f);
            float e0 = a0 - mu, e1 = a1 - mu, e2 = a2 - mu, e3 = a3 - mu;
            float e4 = a4 - mu, e5 = a5 - mu, e6 = a6 - mu;
            float var = (e0*e0 + e1*e1 + e2*e2 + e3*e3 + e4*e4 + e5*e5 + e6*e6) * (1.0f / 7.0f);
            float rs = rsqrtf(var + 1e-5f);
            float* oa = outA + (size_t)(b * SEQ + rbase + rloc0 + s * 32) * 7;
            oa[0] = e0 * rs * g0 + b0;
            oa[1] = e1 * rs * g1 + b1;
            oa[2] = e2 * rs * g2 + b2;
            oa[3] = e3 * rs * g3 + b3;
            oa[4] = e4 * rs * g4 + b4;
            oa[5] = e5 * rs * g5 + b5;
            oa[6] = e6 * rs * g6 + b6;
        }
    }

    // ---- Phase B: lane owns t-quad, STG.128 coalesced weight stores ----
    if (outW) {
        const int tb = warp * 128;        // warp's 128 t-columns
        unsigned long long pt[4][4];
#pragma unroll
        for (int j = 0; j < 4; j++) {
            const int t = tb + lane * 4 + j;
            const float4 ta = sP[t * 2 + 0];
            const float4 tc = sP[t * 2 + 1];
            pt[j][0] = pk2(ta.x, ta.y);
            pt[j][1] = pk2(ta.z, ta.w);
            pt[j][2] = pk2(tc.x, tc.y);
            pt[j][3] = pk2(tc.z, tc.w);
        }
        float* outBase = outW + ((size_t)(b * SEQ + rbase)) * SEQ + tb;

#pragma unroll 2
        for (int r = 0; r < ROWS_CTA; r++) {
            const float4 lo = sP[(rbase + r) * 2 + 0];   // uniform loads
            const float4 hi = sP[(rbase + r) * 2 + 1];
            const unsigned long long lv2 = pk2(slinv[r], 0.f);
            const unsigned long long r0 = pk2(lo.x, lo.y);
            const unsigned long long r1 = pk2(lo.z, lo.w);
            const unsigned long long r2 = pk2(hi.x, hi.y);
            const unsigned long long r3 = pk2(hi.z, hi.w);   // pad slot is 0
            float4 wv;
            {
                unsigned long long z2 = fma2_(r0, pt[0][0], lv2);
                z2 = fma2_(r1, pt[0][1], z2);
                z2 = fma2_(r2, pt[0][2], z2);
                z2 = fma2_(r3, pt[0][3], z2);
                float za, zb; upk2(z2, za, zb);
                wv.x = ex2f(za + zb);
            }
            {
                unsigned long long z2 = fma2_(r0, pt[1][0], lv2);
                z2 = fma2_(r1, pt[1][1], z2);
                z2 = fma2_(r2, pt[1][2], z2);
                z2 = fma2_(r3, pt[1][3], z2);
                float za, zb; upk2(z2, za, zb);
                wv.y = ex2f(za + zb);
            }
            {
                unsigned long long z2 = fma2_(r0, pt[2][0], lv2);
                z2 = fma2_(r1, pt[2][1], z2);
                z2 = fma2_(r2, pt[2][2], z2);
                z2 = fma2_(r3, pt[2][3], z2);
                float za, zb; upk2(z2, za, zb);
                wv.z = ex2f(za + zb);
            }
            {
                unsigned long long z2 = fma2_(r0, pt[3][0], lv2);
                z2 = fma2_(r1, pt[3][1], z2);
                z2 = fma2_(r2, pt[3][2], z2);
                z2 = fma2_(r3, pt[3][3], z2);
                float za, zb; upk2(z2, za, zb);
                wv.w = ex2f(za + zb);
            }
            *reinterpret_cast<float4*>(outBase + (size_t)r * SEQ + lane * 4) = wv;
        }
    }
}

extern "C" void kernel_launch(void* const* d_in, const int* in_sizes, int n_in,
                              void* d_out, int out_size) {
    const float* features = (const float*)d_in[0];
    const float* W        = (const float*)d_in[1];
    const float* bias     = (const float*)d_in[2];
    const float* abias    = (const float*)d_in[3];
    const float* gamma    = (const float*)d_in[4];
    const float* beta     = (const float*)d_in[5];

    float* out = (float*)d_out;
    const long long nA = (long long)BATCH * SEQ * DIM;       // 917504
    const long long nW = (long long)BATCH * SEQ * SEQ;       // 67108864
    float* outA = nullptr;
    float* outW = nullptr;
    long long total = (long long)out_size;
    if (total == nA + nW)      { outA = out; outW = out + nA; }
    else if (total == nW)      { outW = out; }
    else if (total == nA)      { outA = out; }
    else                       { outA = out; outW = out + nA; }

    attn_kernel<<<dim3(2, BATCH), THREADS>>>(features, W, bias, abias,
                                             gamma, beta, outA, outW);
}

// round 10
// speedup vs baseline: 2.0377x; 1.0082x over previous
#include <cuda_runtime.h>

#define BATCH 256
#define SEQ   512
#define DIM   7
#define THREADS 128
#define RPT     2            // rows per thread (phase A)
#define ROWS_CTA 256         // rows covered per CTA (half batch)

typedef unsigned long long u64;

// ---------- packed f32x2 helpers (Blackwell-only, PTX required) ----------
__device__ __forceinline__ u64 pk2(float a, float b) {
    u64 r;
    asm("mov.b64 %0, {%1, %2};" : "=l"(r) : "f"(a), "f"(b));
    return r;
}
__device__ __forceinline__ void upk2(u64 v, float& a, float& b) {
    asm("mov.b64 {%0, %1}, %2;" : "=f"(a), "=f"(b) : "l"(v));
}
__device__ __forceinline__ u64 fma2_(u64 a, u64 b, u64 c) {
    u64 d;
    asm("fma.rn.f32x2 %0, %1, %2, %3;" : "=l"(d) : "l"(a), "l"(b), "l"(c));
    return d;
}
__device__ __forceinline__ u64 mul2_(u64 a, u64 b) {
    u64 d;
    asm("mul.rn.f32x2 %0, %1, %2;" : "=l"(d) : "l"(a), "l"(b));
    return d;
}
__device__ __forceinline__ float ex2f(float x) {
    float y; asm("ex2.approx.f32 %0, %1;" : "=f"(y) : "f"(x)); return y;
}
__device__ __forceinline__ float lg2f(float x) {
    float y; asm("lg2.approx.f32 %0, %1;" : "=f"(y) : "f"(x)); return y;
}
__device__ __forceinline__ float rcpf(float x) {
    float y; asm("rcp.approx.f32 %0, %1;" : "=f"(y) : "f"(x)); return y;
}

// ---------- Single fused kernel ----------
__global__ __launch_bounds__(THREADS) void attn_kernel(
    const float* __restrict__ feat,
    const float* __restrict__ Wm,
    const float* __restrict__ bia,
    const float* __restrict__ abias,
    const float* __restrict__ gamma,
    const float* __restrict__ beta,
    float* __restrict__ outA, float* __restrict__ outW) {
    __shared__ float4 sP[SEQ * 2];        // 16 KB (pre-scaled projected, pad 0)
    __shared__ float4 sV[SEQ * 2];        // 16 KB (biased values, pad 1.0 -> row sums)
    __shared__ float  slinv[ROWS_CTA];    // -log2(rowsum)

    const int b    = blockIdx.y;
    const int half = blockIdx.x;          // 0/1 -> which 256 rows
    const int tid  = threadIdx.x;
    const int lane = tid & 31;
    const int warp = tid >> 5;

    // ---- Fused prep/staging: read features, project, scale, fill smem ----
    {
        const float SC = 0.7384116545f;   // sqrt(log2(e)/sqrt(7))
        float wr[7][7], br[7], ar[7];
#pragma unroll
        for (int e = 0; e < 7; e++) {
            br[e] = __ldg(&bia[e]);
            ar[e] = __ldg(&abias[e]);
#pragma unroll
            for (int d = 0; d < 7; d++) wr[e][d] = __ldg(&Wm[e * 7 + d]);
        }
#pragma unroll
        for (int i = 0; i < 4; i++) {
            const int r = tid + i * THREADS;          // 0..511
            const float* fp = feat + ((size_t)b * SEQ + r) * 7;
            float f[7];
#pragma unroll
            for (int d = 0; d < 7; d++) f[d] = fp[d] + ar[d];
            float p[7];
#pragma unroll
            for (int e = 0; e < 7; e++) {
                float s = br[e];
#pragma unroll
                for (int d = 0; d < 7; d++) s = fmaf(f[d], wr[e][d], s);
                p[e] = s * SC;
            }
            sV[r * 2 + 0] = make_float4(f[0], f[1], f[2], f[3]);
            sV[r * 2 + 1] = make_float4(f[4], f[5], f[6], 1.0f);  // pad=1 -> sum slot
            sP[r * 2 + 0] = make_float4(p[0], p[1], p[2], p[3]);
            sP[r * 2 + 1] = make_float4(p[4], p[5], p[6], 0.f);
        }
    }
    __syncthreads();

    // Direct 64-bit pair views of the tables (LDS.128 -> f32x2 operands, no MOVs).
    const ulonglong2* sPu = reinterpret_cast<const ulonglong2*>(sP);
    const ulonglong2* sVu = reinterpret_cast<const ulonglong2*>(sV);

    const int rbase = half * ROWS_CTA;                  // CTA row offset in batch
    const int rloc0 = warp * (RPT * 32) + lane;         // local row of slot 0

    u64 q[RPT][4];
#pragma unroll
    for (int s = 0; s < RPT; s++) {
        const int r = rbase + rloc0 + s * 32;
        const ulonglong2 qa = sPu[r * 2 + 0];
        const ulonglong2 qb = sPu[r * 2 + 1];
        q[s][0] = qa.x; q[s][1] = qa.y; q[s][2] = qb.x; q[s][3] = qb.y;  // pad 0
    }

    // ---- Phase A: attended accumulators; row sum rides in acc[s][3].hi ----
    u64 acc[RPT][4];
#pragma unroll
    for (int s = 0; s < RPT; s++) {
#pragma unroll
        for (int j = 0; j < 4; j++) acc[s][j] = 0ull;
    }

#pragma unroll 8
    for (int t = 0; t < SEQ; t++) {
        const ulonglong2 pA = sPu[t * 2 + 0];
        const ulonglong2 pB = sPu[t * 2 + 1];
        const ulonglong2 vA = sVu[t * 2 + 0];
        const ulonglong2 vB = sVu[t * 2 + 1];   // vB.y hi = 1.0 (sum slot)
#pragma unroll
        for (int s = 0; s < RPT; s++) {
            u64 z2 = mul2_(q[s][0], pA.x);
            z2 = fma2_(q[s][1], pA.y, z2);
            z2 = fma2_(q[s][2], pB.x, z2);
            z2 = fma2_(q[s][3], pB.y, z2);
            float za, zb; upk2(z2, za, zb);
            const float e = ex2f(za + zb);
            const u64 ee = pk2(e, e);
            acc[s][0] = fma2_(ee, vA.x, acc[s][0]);
            acc[s][1] = fma2_(ee, vA.y, acc[s][1]);
            acc[s][2] = fma2_(ee, vB.x, acc[s][2]);
            acc[s][3] = fma2_(ee, vB.y, acc[s][3]);
        }
    }

    float sum[RPT];
#pragma unroll
    for (int s = 0; s < RPT; s++) {
        float a6, sm; upk2(acc[s][3], a6, sm);
        sum[s] = sm;
        slinv[rloc0 + s * 32] = -lg2f(sm);
    }
    __syncthreads();

    // ---- Attended + LayerNorm (fully per-lane) ----
    if (outA) {
        float g0 = __ldg(&gamma[0]), g1 = __ldg(&gamma[1]), g2 = __ldg(&gamma[2]),
              g3 = __ldg(&gamma[3]), g4 = __ldg(&gamma[4]), g5 = __ldg(&gamma[5]),
              g6 = __ldg(&gamma[6]);
        float b0 = __ldg(&beta[0]), b1 = __ldg(&beta[1]), b2 = __ldg(&beta[2]),
              b3 = __ldg(&beta[3]), b4 = __ldg(&beta[4]), b5 = __ldg(&beta[5]),
              b6 = __ldg(&beta[6]);
#pragma unroll
        for (int s = 0; s < RPT; s++) {
            float a0, a1, a2, a3, a4, a5, a6, ax;
            upk2(acc[s][0], a0, a1);
            upk2(acc[s][1], a2, a3);
            upk2(acc[s][2], a4, a5);
            upk2(acc[s][3], a6, ax);
            float iv = rcpf(sum[s]);
            a0 *= iv; a1 *= iv; a2 *= iv; a3 *= iv; a4 *= iv; a5 *= iv; a6 *= iv;
            float mu = (a0 + a1 + a2 + a3 + a4 + a5 + a6) * (1.0f / 7.0f);
            float e0 = a0 - mu, e1 = a1 - mu, e2 = a2 - mu, e3 = a3 - mu;
            float e4 = a4 - mu, e5 = a5 - mu, e6 = a6 - mu;
            float var = (e0*e0 + e1*e1 + e2*e2 + e3*e3 + e4*e4 + e5*e5 + e6*e6) * (1.0f / 7.0f);
            float rs = rsqrtf(var + 1e-5f);
            float* oa = outA + (size_t)(b * SEQ + rbase + rloc0 + s * 32) * 7;
            oa[0] = e0 * rs * g0 + b0;
            oa[1] = e1 * rs * g1 + b1;
            oa[2] = e2 * rs * g2 + b2;
            oa[3] = e3 * rs * g3 + b3;
            oa[4] = e4 * rs * g4 + b4;
            oa[5] = e5 * rs * g5 + b5;
            oa[6] = e6 * rs * g6 + b6;
        }
    }

    // ---- Phase B: lane owns t-quad, STG.128 coalesced weight stores ----
    if (outW) {
        const int tb = warp * 128;        // warp's 128 t-columns
        u64 pt[4][4];
#pragma unroll
        for (int j = 0; j < 4; j++) {
            const int t = tb + lane * 4 + j;
            const ulonglong2 ta = sPu[t * 2 + 0];
            const ulonglong2 tc = sPu[t * 2 + 1];
            pt[j][0] = ta.x; pt[j][1] = ta.y; pt[j][2] = tc.x; pt[j][3] = tc.y;
        }
        float* outBase = outW + ((size_t)(b * SEQ + rbase)) * SEQ + tb;

#pragma unroll 2
        for (int r = 0; r < ROWS_CTA; r++) {
            const ulonglong2 rA = sPu[(rbase + r) * 2 + 0];   // uniform loads
            const ulonglong2 rB = sPu[(rbase + r) * 2 + 1];
            const u64 lv2 = pk2(slinv[r], 0.f);
            const u64 r0 = rA.x, r1 = rA.y, r2 = rB.x, r3 = rB.y;  // pad 0
            float4 wv;
            {
                u64 z2 = fma2_(r0, pt[0][0], lv2);
                z2 = fma2_(r1, pt[0][1], z2);
                z2 = fma2_(r2, pt[0][2], z2);
                z2 = fma2_(r3, pt[0][3], z2);
                float za, zb; upk2(z2, za, zb);
                wv.x = ex2f(za + zb);
            }
            {
                u64 z2 = fma2_(r0, pt[1][0], lv2);
                z2 = fma2_(r1, pt[1][1], z2);
                z2 = fma2_(r2, pt[1][2], z2);
                z2 = fma2_(r3, pt[1][3], z2);
                float za, zb; upk2(z2, za, zb);
                wv.y = ex2f(za + zb);
            }
            {
                u64 z2 = fma2_(r0, pt[2][0], lv2);
                z2 = fma2_(r1, pt[2][1], z2);
                z2 = fma2_(r2, pt[2][2], z2);
                z2 = fma2_(r3, pt[2][3], z2);
                float za, zb; upk2(z2, za, zb);
                wv.z = ex2f(za + zb);
            }
            {
                u64 z2 = fma2_(r0, pt[3][0], lv2);
                z2 = fma2_(r1, pt[3][1], z2);
                z2 = fma2_(r2, pt[3][2], z2);
                z2 = fma2_(r3, pt[3][3], z2);
                float za, zb; upk2(z2, za, zb);
                wv.w = ex2f(za + zb);
            }
            *reinterpret_cast<float4*>(outBase + (size_t)r * SEQ + lane * 4) = wv;
        }
    }
}

extern "C" void kernel_launch(void* const* d_in, const int* in_sizes, int n_in,
                              void* d_out, int out_size) {
    const float* features = (const float*)d_in[0];
    const float* W        = (const float*)d_in[1];
    const float* bias     = (const float*)d_in[2];
    const float* abias    = (const float*)d_in[3];
    const float* gamma    = (const float*)d_in[4];
    const float* beta     = (const float*)d_in[5];

    float* out = (float*)d_out;
    const long long nA = (long long)BATCH * SEQ * DIM;       // 917504
    const long long nW = (long long)BATCH * SEQ * SEQ;       // 67108864
    float* outA = nullptr;
    float* outW = nullptr;
    long long total = (long long)out_size;
    if (total == nA + nW)      { outA = out; outW = out + nA; }
    else if (total == nW)      { outW = out; }
    else if (total == nA)      { outA = out; }
    else                       { outA = out; outW = out + nA; }

    attn_kernel<<<dim3(2, BATCH), THREADS>>>(features, W, bias, abias,
                                             gamma, beta, outA, outW);
}

// round 11
// speedup vs baseline: 2.2491x; 1.1037x over previous
#include <cuda_runtime.h>

#define BATCH 256
#define SEQ   512
#define DIM   7
#define THREADS 128
#define RPT     2            // rows per thread (phase A)
#define ROWS_CTA 128         // rows covered per CTA (quarter batch)

typedef unsigned long long u64;

// ---------- packed f32x2 helpers (Blackwell-only, PTX required) ----------
__device__ __forceinline__ u64 pk2(float a, float b) {
    u64 r;
    asm("mov.b64 %0, {%1, %2};" : "=l"(r) : "f"(a), "f"(b));
    return r;
}
__device__ __forceinline__ void upk2(u64 v, float& a, float& b) {
    asm("mov.b64 {%0, %1}, %2;" : "=f"(a), "=f"(b) : "l"(v));
}
__device__ __forceinline__ u64 fma2_(u64 a, u64 b, u64 c) {
    u64 d;
    asm("fma.rn.f32x2 %0, %1, %2, %3;" : "=l"(d) : "l"(a), "l"(b), "l"(c));
    return d;
}
__device__ __forceinline__ u64 mul2_(u64 a, u64 b) {
    u64 d;
    asm("mul.rn.f32x2 %0, %1, %2;" : "=l"(d) : "l"(a), "l"(b));
    return d;
}
__device__ __forceinline__ u64 add2_(u64 a, u64 b) {
    u64 d;
    asm("add.rn.f32x2 %0, %1, %2;" : "=l"(d) : "l"(a), "l"(b));
    return d;
}
__device__ __forceinline__ float ex2f(float x) {
    float y; asm("ex2.approx.f32 %0, %1;" : "=f"(y) : "f"(x)); return y;
}
__device__ __forceinline__ float lg2f(float x) {
    float y; asm("lg2.approx.f32 %0, %1;" : "=f"(y) : "f"(x)); return y;
}
__device__ __forceinline__ float rcpf(float x) {
    float y; asm("rcp.approx.f32 %0, %1;" : "=f"(y) : "f"(x)); return y;
}

// ---------- Single fused kernel ----------
__global__ __launch_bounds__(THREADS, 5) void attn_kernel(
    const float* __restrict__ feat,
    const float* __restrict__ Wm,
    const float* __restrict__ bia,
    const float* __restrict__ abias,
    const float* __restrict__ gamma,
    const float* __restrict__ beta,
    float* __restrict__ outA, float* __restrict__ outW) {
    __shared__ float4 sP[SEQ * 2];          // 16 KB (pre-scaled projected, pad 0)
    __shared__ float4 sV[SEQ * 2];          // 16 KB (biased values, pad 1.0 -> row sums)
    __shared__ u64    part[2][64][4];       // 4 KB  (t-half partial accumulators)
    __shared__ float  slinv[ROWS_CTA];      // -log2(rowsum)

    const int b    = blockIdx.y;
    const int quad = blockIdx.x;            // 0..3 -> which 128 rows
    const int tid  = threadIdx.x;
    const int lane = tid & 31;
    const int warp = tid >> 5;
    const int pair = warp >> 1;             // 0/1: row group within CTA
    const int th   = warp & 1;              // 0/1: t-half

    // ---- Fused prep/staging: read features, project, scale, fill smem ----
    {
        const float SC = 0.7384116545f;     // sqrt(log2(e)/sqrt(7))
        float wr[7][7], br[7], ar[7];
#pragma unroll
        for (int e = 0; e < 7; e++) {
            br[e] = __ldg(&bia[e]);
            ar[e] = __ldg(&abias[e]);
#pragma unroll
            for (int d = 0; d < 7; d++) wr[e][d] = __ldg(&Wm[e * 7 + d]);
        }
#pragma unroll
        for (int i = 0; i < 4; i++) {
            const int r = tid + i * THREADS;            // 0..511
            const float* fp = feat + ((size_t)b * SEQ + r) * 7;
            float f[7];
#pragma unroll
            for (int d = 0; d < 7; d++) f[d] = fp[d] + ar[d];
            float p[7];
#pragma unroll
            for (int e = 0; e < 7; e++) {
                float s = br[e];
#pragma unroll
                for (int d = 0; d < 7; d++) s = fmaf(f[d], wr[e][d], s);
                p[e] = s * SC;
            }
            sV[r * 2 + 0] = make_float4(f[0], f[1], f[2], f[3]);
            sV[r * 2 + 1] = make_float4(f[4], f[5], f[6], 1.0f);  // pad=1 -> sum slot
            sP[r * 2 + 0] = make_float4(p[0], p[1], p[2], p[3]);
            sP[r * 2 + 1] = make_float4(p[4], p[5], p[6], 0.f);
        }
    }
    __syncthreads();

    // Direct 64-bit pair views of the tables (LDS.128 -> f32x2 operands).
    const ulonglong2* sPu = reinterpret_cast<const ulonglong2*>(sP);
    const ulonglong2* sVu = reinterpret_cast<const ulonglong2*>(sV);

    const int rbase = quad * ROWS_CTA;                  // CTA row offset in batch
    const int rloc0 = pair * 64 + lane;                 // local row of slot 0 (s adds 32)

    u64 q[RPT][4];
#pragma unroll
    for (int s = 0; s < RPT; s++) {
        const int r = rbase + rloc0 + s * 32;
        const ulonglong2 qa = sPu[r * 2 + 0];
        const ulonglong2 qb = sPu[r * 2 + 1];
        q[s][0] = qa.x; q[s][1] = qa.y; q[s][2] = qb.x; q[s][3] = qb.y;  // pad 0
    }

    // ---- Phase A (t-half): attended accumulators; row sum rides in acc[s][3].hi ----
    u64 acc[RPT][4];
#pragma unroll
    for (int s = 0; s < RPT; s++) {
#pragma unroll
        for (int j = 0; j < 4; j++) acc[s][j] = 0ull;
    }

    const int t0 = th * 256;
#pragma unroll 8
    for (int ti = 0; ti < 256; ti++) {
        const int t = t0 + ti;
        const ulonglong2 pA = sPu[t * 2 + 0];
        const ulonglong2 pB = sPu[t * 2 + 1];
        const ulonglong2 vA = sVu[t * 2 + 0];
        const ulonglong2 vB = sVu[t * 2 + 1];   // vB.y hi = 1.0 (sum slot)
#pragma unroll
        for (int s = 0; s < RPT; s++) {
            u64 z2 = mul2_(q[s][0], pA.x);
            z2 = fma2_(q[s][1], pA.y, z2);
            z2 = fma2_(q[s][2], pB.x, z2);
            z2 = fma2_(q[s][3], pB.y, z2);
            float za, zb; upk2(z2, za, zb);
            const float e = ex2f(za + zb);
            const u64 ee = pk2(e, e);
            acc[s][0] = fma2_(ee, vA.x, acc[s][0]);
            acc[s][1] = fma2_(ee, vA.y, acc[s][1]);
            acc[s][2] = fma2_(ee, vB.x, acc[s][2]);
            acc[s][3] = fma2_(ee, vB.y, acc[s][3]);
        }
    }

    // ---- Merge t-halves: th=1 publishes, th=0 combines and finishes rows ----
    if (th == 1) {
#pragma unroll
        for (int s = 0; s < RPT; s++) {
#pragma unroll
            for (int j = 0; j < 4; j++) part[pair][s * 32 + lane][j] = acc[s][j];
        }
    }
    __syncthreads();

    if (th == 0) {
        float sum[RPT];
#pragma unroll
        for (int s = 0; s < RPT; s++) {
#pragma unroll
            for (int j = 0; j < 4; j++)
                acc[s][j] = add2_(acc[s][j], part[pair][s * 32 + lane][j]);
            float a6, sm; upk2(acc[s][3], a6, sm);
            sum[s] = sm;
            slinv[rloc0 + s * 32] = -lg2f(sm);
        }

        // ---- Attended + LayerNorm (fully per-lane) ----
        if (outA) {
            float g0 = __ldg(&gamma[0]), g1 = __ldg(&gamma[1]), g2 = __ldg(&gamma[2]),
                  g3 = __ldg(&gamma[3]), g4 = __ldg(&gamma[4]), g5 = __ldg(&gamma[5]),
                  g6 = __ldg(&gamma[6]);
            float b0 = __ldg(&beta[0]), b1 = __ldg(&beta[1]), b2 = __ldg(&beta[2]),
                  b3 = __ldg(&beta[3]), b4 = __ldg(&beta[4]), b5 = __ldg(&beta[5]),
                  b6 = __ldg(&beta[6]);
#pragma unroll
            for (int s = 0; s < RPT; s++) {
                float a0, a1, a2, a3, a4, a5, a6, ax;
                upk2(acc[s][0], a0, a1);
                upk2(acc[s][1], a2, a3);
                upk2(acc[s][2], a4, a5);
                upk2(acc[s][3], a6, ax);
                float iv = rcpf(sum[s]);
                a0 *= iv; a1 *= iv; a2 *= iv; a3 *= iv; a4 *= iv; a5 *= iv; a6 *= iv;
                float mu = (a0 + a1 + a2 + a3 + a4 + a5 + a6) * (1.0f / 7.0f);
                float e0 = a0 - mu, e1 = a1 - mu, e2 = a2 - mu, e3 = a3 - mu;
                float e4 = a4 - mu, e5 = a5 - mu, e6 = a6 - mu;
                float var = (e0*e0 + e1*e1 + e2*e2 + e3*e3 + e4*e4 + e5*e5 + e6*e6) * (1.0f / 7.0f);
                float rs = rsqrtf(var + 1e-5f);
                float* oa = outA + (size_t)(b * SEQ + rbase + rloc0 + s * 32) * 7;
                oa[0] = e0 * rs * g0 + b0;
                oa[1] = e1 * rs * g1 + b1;
                oa[2] = e2 * rs * g2 + b2;
                oa[3] = e3 * rs * g3 + b3;
                oa[4] = e4 * rs * g4 + b4;
                oa[5] = e5 * rs * g5 + b5;
                oa[6] = e6 * rs * g6 + b6;
            }
        }
    }
    __syncthreads();

    // ---- Phase B: lane owns t-quad, STG.128 coalesced weight stores ----
    if (outW) {
        const int tb = warp * 128;        // warp's 128 t-columns
        u64 pt[4][4];
#pragma unroll
        for (int j = 0; j < 4; j++) {
            const int t = tb + lane * 4 + j;
            const ulonglong2 ta = sPu[t * 2 + 0];
            const ulonglong2 tc = sPu[t * 2 + 1];
            pt[j][0] = ta.x; pt[j][1] = ta.y; pt[j][2] = tc.x; pt[j][3] = tc.y;
        }
        float* outBase = outW + ((size_t)(b * SEQ + rbase)) * SEQ + tb;

#pragma unroll 2
        for (int r = 0; r < ROWS_CTA; r++) {
            const ulonglong2 rA = sPu[(rbase + r) * 2 + 0];   // uniform loads
            const ulonglong2 rB = sPu[(rbase + r) * 2 + 1];
            const u64 lv2 = pk2(slinv[r], 0.f);
            const u64 r0 = rA.x, r1 = rA.y, r2 = rB.x, r3 = rB.y;  // pad 0
            float4 wv;
            {
                u64 z2 = fma2_(r0, pt[0][0], lv2);
                z2 = fma2_(r1, pt[0][1], z2);
                z2 = fma2_(r2, pt[0][2], z2);
                z2 = fma2_(r3, pt[0][3], z2);
                float za, zb; upk2(z2, za, zb);
                wv.x = ex2f(za + zb);
            }
            {
                u64 z2 = fma2_(r0, pt[1][0], lv2);
                z2 = fma2_(r1, pt[1][1], z2);
                z2 = fma2_(r2, pt[1][2], z2);
                z2 = fma2_(r3, pt[1][3], z2);
                float za, zb; upk2(z2, za, zb);
                wv.y = ex2f(za + zb);
            }
            {
                u64 z2 = fma2_(r0, pt[2][0], lv2);
                z2 = fma2_(r1, pt[2][1], z2);
                z2 = fma2_(r2, pt[2][2], z2);
                z2 = fma2_(r3, pt[2][3], z2);
                float za, zb; upk2(z2, za, zb);
                wv.z = ex2f(za + zb);
            }
            {
                u64 z2 = fma2_(r0, pt[3][0], lv2);
                z2 = fma2_(r1, pt[3][1], z2);
                z2 = fma2_(r2, pt[3][2], z2);
                z2 = fma2_(r3, pt[3][3], z2);
                float za, zb; upk2(z2, za, zb);
                wv.w = ex2f(za + zb);
            }
            *reinterpret_cast<float4*>(outBase + (size_t)r * SEQ + lane * 4) = wv;
        }
    }
}

extern "C" void kernel_launch(void* const* d_in, const int* in_sizes, int n_in,
                              void* d_out, int out_size) {
    const float* features = (const float*)d_in[0];
    const float* W        = (const float*)d_in[1];
    const float* bias     = (const float*)d_in[2];
    const float* abias    = (const float*)d_in[3];
    const float* gamma    = (const float*)d_in[4];
    const float* beta     = (const float*)d_in[5];

    float* out = (float*)d_out;
    const long long nA = (long long)BATCH * SEQ * DIM;       // 917504
    const long long nW = (long long)BATCH * SEQ * SEQ;       // 67108864
    float* outA = nullptr;
    float* outW = nullptr;
    long long total = (long long)out_size;
    if (total == nA + nW)      { outA = out; outW = out + nA; }
    else if (total == nW)      { outW = out; }
    else if (total == nA)      { outA = out; }
    else                       { outA = out; outW = out + nA; }

    attn_kernel<<<dim3(4, BATCH), THREADS>>>(features, W, bias, abias,
                                             gamma, beta, outA, outW);
}